// round 14
// baseline (speedup 1.0000x reference)
#include <cuda_runtime.h>
#include <cuda_fp16.h>
#include <mma.h>
#include <cstdint>

using namespace nvcuda;

// Fixed shapes
#define B_      2
#define L_      512
#define D_      256
#define TILE    64
#define THREADS 512
#define SST     264                      // fp16 row stride: 256 + 8 pad (528B)
#define TEL     (TILE * SST)
#define SMEM_BYTES (2 * TEL * 2)         // 67584 B

// out[b,i,j] = sum_d x[b,i,d]*w1[d]*x[b,j,d] + bias   (symmetric)
// (lin_i - lin_j cancels under (P+P^T)/2; w2 = W[D:,0] dead.)
// fp16 single product, f32 accumulate; A = fp16(x) * fp16(w1) via HMUL2.
// rel err ~4e-4 < 1e-3.

__device__ __forceinline__ uint32_t h2(float a, float b) {
    __half2 h = __floats2half2_rn(a, b);
    return *reinterpret_cast<uint32_t*>(&h);
}
// pack 2 float4 -> uint4 of 8 fp16
__device__ __forceinline__ uint4 pack8(float4 f0, float4 f1) {
    uint4 v;
    v.x = h2(f0.x, f0.y);
    v.y = h2(f0.z, f0.w);
    v.z = h2(f1.x, f1.y);
    v.w = h2(f1.z, f1.w);
    return v;
}
// elementwise fp16x2 multiply of packed data by packed weights
__device__ __forceinline__ uint4 mulw(uint4 v, uint4 w) {
    uint4 r;
    *(__half2*)&r.x = __hmul2(*(__half2*)&v.x, *(__half2*)&w.x);
    *(__half2*)&r.y = __hmul2(*(__half2*)&v.y, *(__half2*)&w.y);
    *(__half2*)&r.z = __hmul2(*(__half2*)&v.z, *(__half2*)&w.z);
    *(__half2*)&r.w = __hmul2(*(__half2*)&v.w, *(__half2*)&w.w);
    return r;
}

__global__ __launch_bounds__(THREADS, 1)
void fused_pairwise_kernel(const float* __restrict__ x,
                           const float* __restrict__ W,
                           const float* __restrict__ bias_p,
                           float* __restrict__ out) {
    extern __shared__ __align__(16) __half smem[];
    __half* sB = smem;            // fp16(x), j-strip rows
    __half* sA = smem + TEL;      // fp16(x)*fp16(w1), i-strip rows

    const int bz  = blockIdx.z;
    const int ti  = blockIdx.y;
    const int tj  = blockIdx.x;
    const int tid = threadIdx.x;
    const int warp = tid >> 5;

    const float4* A4 = (const float4*)(x + (size_t)(bz * L_ + ti * TILE) * D_);
    const float4* B4 = (const float4*)(x + (size_t)(bz * L_ + tj * TILE) * D_);
    const float4* W4 = (const float4*)W;  // w1 = W[:256] -> f4 cols 0..63

    // ---------- chunk-1 warps (8-15): issue ALL gmem loads at t=0 ----------
    float4 c1f[8];                 // 8 rows x 2 f4 staged (4 rows per reg pair)
    uint4  c1w;                    // packed fp16 w1 (A threads only)
    int c1_g = 0, c1_cf4 = 0, c1_rblk = 0;
    if (warp >= 8) {
        const int u    = tid - 256;        // 0..255
        c1_g    = u >> 7;                  // 0 -> B (w8-11), 1 -> A (w12-15)
        const int uu   = u & 127;
        c1_cf4  = 32 + (uu & 15) * 2;      // f4 cols 32..62
        c1_rblk = uu >> 4;                 // 0..7 -> rows rblk*8+p
        const float4* S = c1_g ? A4 : B4;
        #pragma unroll
        for (int p = 0; p < 4; p++) {      // stage first 4 of 8 rows
            int row = c1_rblk * 8 + p;
            c1f[2*p]   = S[row * 64 + c1_cf4];
            c1f[2*p+1] = S[row * 64 + c1_cf4 + 1];
        }
        if (c1_g) {
            float4 w0 = __ldg(&W4[c1_cf4]);
            float4 w1v = __ldg(&W4[c1_cf4 + 1]);
            c1w = pack8(w0, w1v);
        }
    }

    // ---------- phase A: chunk 0 (f4 cols 0..31) by warps 0-7 ----------
    if (warp < 8) {
        const int g    = (tid >> 7) & 1;   // w0-3 -> B, w4-7 -> A
        const int u    = tid & 127;
        const int cf4  = (u & 15) * 2;     // f4 cols 0..30
        const int rblk = u >> 4;           // 0..7 -> rows rblk*8+p
        const float4* S = g ? A4 : B4;
        __half* dst = g ? sA : sB;
        uint4 wp;
        if (g) {
            float4 w0 = __ldg(&W4[cf4]);
            float4 w1v = __ldg(&W4[cf4 + 1]);
            wp = pack8(w0, w1v);
        }
        #pragma unroll
        for (int p = 0; p < 8; p++) {
            int row = rblk * 8 + p;
            float4 f0 = S[row * 64 + cf4];
            float4 f1 = S[row * 64 + cf4 + 1];
            uint4 v = pack8(f0, f1);
            if (g) v = mulw(v, wp);
            *(uint4*)&dst[row * SST + cf4 * 4] = v;
        }
    }
    __syncthreads();

    // ---------- phase B: MMA(chunk0) by warps 0-3 || chunk-1 STS by 8-15 ----
    wmma::fragment<wmma::accumulator, 16, 16, 16, float> acc[2][2];
    const int wr = (warp >> 1) & 1;
    const int wc = warp & 1;
    const float bias = (warp < 4) ? __ldg(bias_p) : 0.0f;

    if (warp < 4) {
        #pragma unroll
        for (int r = 0; r < 2; r++)
            #pragma unroll
            for (int c = 0; c < 2; c++)
                wmma::fill_fragment(acc[r][c], bias);   // bias folded in

        const __half* Ab = sA + (wr * 32) * SST;
        const __half* Bb = sB + (wc * 32) * SST;
        #pragma unroll
        for (int kk = 0; kk < 128; kk += 16) {
            wmma::fragment<wmma::matrix_a, 16, 16, 16, __half, wmma::row_major> af[2];
            wmma::fragment<wmma::matrix_b, 16, 16, 16, __half, wmma::col_major> bf[2];
            #pragma unroll
            for (int r = 0; r < 2; r++)
                wmma::load_matrix_sync(af[r], Ab + r * 16 * SST + kk, SST);
            #pragma unroll
            for (int c = 0; c < 2; c++)
                wmma::load_matrix_sync(bf[c], Bb + c * 16 * SST + kk, SST);
            #pragma unroll
            for (int r = 0; r < 2; r++)
                #pragma unroll
                for (int c = 0; c < 2; c++)
                    wmma::mma_sync(acc[r][c], af[r], bf[c], acc[r][c]);
        }
    } else if (warp >= 8) {
        __half* dst = c1_g ? sA : sB;
        const float4* S = c1_g ? A4 : B4;
        // rows 0-3: already staged; convert+STS, then rows 4-7
        #pragma unroll
        for (int p = 0; p < 4; p++) {
            int row = c1_rblk * 8 + p;
            uint4 v = pack8(c1f[2*p], c1f[2*p+1]);
            if (c1_g) v = mulw(v, c1w);
            *(uint4*)&dst[row * SST + c1_cf4 * 4] = v;
        }
        #pragma unroll
        for (int p = 4; p < 8; p++) {
            int row = c1_rblk * 8 + p;
            float4 f0 = S[row * 64 + c1_cf4];
            float4 f1 = S[row * 64 + c1_cf4 + 1];
            uint4 v = pack8(f0, f1);
            if (c1_g) v = mulw(v, c1w);
            *(uint4*)&dst[row * SST + c1_cf4 * 4] = v;
        }
    }
    __syncthreads();

    // ---------- phase C: MMA(chunk1) + store (warps 0-3) ----------
    if (warp >= 4) return;

    {
        const __half* Ab = sA + (wr * 32) * SST;
        const __half* Bb = sB + (wc * 32) * SST;
        #pragma unroll
        for (int kk = 128; kk < 256; kk += 16) {
            wmma::fragment<wmma::matrix_a, 16, 16, 16, __half, wmma::row_major> af[2];
            wmma::fragment<wmma::matrix_b, 16, 16, 16, __half, wmma::col_major> bf[2];
            #pragma unroll
            for (int r = 0; r < 2; r++)
                wmma::load_matrix_sync(af[r], Ab + r * 16 * SST + kk, SST);
            #pragma unroll
            for (int c = 0; c < 2; c++)
                wmma::load_matrix_sync(bf[c], Bb + c * 16 * SST + kk, SST);
            #pragma unroll
            for (int r = 0; r < 2; r++)
                #pragma unroll
                for (int c = 0; c < 2; c++)
                    wmma::mma_sync(acc[r][c], af[r], bf[c], acc[r][c]);
        }
    }

    #pragma unroll
    for (int r = 0; r < 2; r++) {
        #pragma unroll
        for (int c = 0; c < 2; c++) {
            int gi = ti * TILE + wr * 32 + r * 16;
            int gj = tj * TILE + wc * 32 + c * 16;
            float* dst = out + (size_t)bz * L_ * L_ + (size_t)gi * L_ + gj;
            wmma::store_matrix_sync(dst, acc[r][c], L_, wmma::mem_row_major);
        }
    }
}

// ---------------------------------------------------------------------------
// d_in[0] = inputs f32 (2,512,256), d_in[1] = W f32 (512,1), d_in[2] = b f32 (1,)
// d_out   = f32 (2,512,512,1)
// ---------------------------------------------------------------------------
extern "C" void kernel_launch(void* const* d_in, const int* in_sizes, int n_in,
                              void* d_out, int out_size) {
    const float* x    = (const float*)d_in[0];
    const float* W    = (const float*)d_in[1];
    const float* bptr = (const float*)d_in[2];
    float* out = (float*)d_out;

    static bool attr_set = false;
    if (!attr_set) {
        cudaFuncSetAttribute(fused_pairwise_kernel,
                             cudaFuncAttributeMaxDynamicSharedMemorySize, SMEM_BYTES);
        attr_set = true;
    }

    dim3 grid(L_ / TILE, L_ / TILE, B_);   // (8, 8, 2) = 128 CTAs, single wave
    fused_pairwise_kernel<<<grid, THREADS, SMEM_BYTES>>>(x, W, bptr, out);
}

// round 15
// speedup vs baseline: 1.2050x; 1.2050x over previous
#include <cuda_runtime.h>
#include <cuda_fp16.h>
#include <mma.h>
#include <cstdint>

using namespace nvcuda;

// Fixed shapes
#define B_      2
#define L_      512
#define D_      256
#define TILE    64
#define THREADS 512
#define SST     264                      // fp16 row stride: 256 + 8 pad (528B)
#define TEL     (TILE * SST)
#define SMEM_BYTES (2 * TEL * 2)         // 67584 B

// out[b,i,j] = sum_d x[b,i,d]*w1[d]*x[b,j,d] + bias   (symmetric)
// (lin_i - lin_j cancels under (P+P^T)/2; w2 = W[D:,0] dead.)
// fp16 single product, f32 accumulate: rel err ~2.9e-4 < 1e-3 (measured).

__device__ __forceinline__ uint32_t h2(float a, float b) {
    __half2 h = __floats2half2_rn(a, b);
    return *reinterpret_cast<uint32_t*>(&h);
}

// convert 2 float4 (8 floats) -> 8 fp16 packed in uint4
__device__ __forceinline__ uint4 pack8(float4 f0, float4 f1) {
    uint4 v;
    v.x = h2(f0.x, f0.y);
    v.y = h2(f0.z, f0.w);
    v.z = h2(f1.x, f1.y);
    v.w = h2(f1.z, f1.w);
    return v;
}
__device__ __forceinline__ float4 mul4(float4 a, float4 w) {
    a.x *= w.x; a.y *= w.y; a.z *= w.z; a.w *= w.w;
    return a;
}

__global__ __launch_bounds__(THREADS, 1)
void fused_pairwise_kernel(const float* __restrict__ x,
                           const float* __restrict__ W,
                           const float* __restrict__ bias_p,
                           float* __restrict__ out) {
    extern __shared__ __align__(16) __half smem[];
    __half* sB = smem;            // fp16(x), j-strip rows
    __half* sA = smem + TEL;      // fp16(x*w1), i-strip rows

    const int bz  = blockIdx.z;
    const int ti  = blockIdx.y;
    const int tj  = blockIdx.x;
    const int tid = threadIdx.x;
    const int warp = tid >> 5;

    const float bias = __ldg(bias_p);     // prefetch early

    const float4* A4 = (const float4*)(x + (size_t)(bz * L_ + ti * TILE) * D_);
    const float4* B4 = (const float4*)(x + (size_t)(bz * L_ + tj * TILE) * D_);
    const float4* W4 = (const float4*)W;  // w1 = W[:256] -> f4 cols 0..63

    // ================= phase A: chunk 0 (f4 cols 0..31), all 512 threads ====
    {
        const int g    = tid >> 8;         // 0 -> B, 1 -> A
        const int u    = tid & 255;
        const int pcol = u & 15;           // pair index (2 f4) within chunk
        const int rblk = u >> 4;           // 0..15 -> rows rblk*4+p
        const int cf4  = pcol * 2;         // f4 col 0..30
        const float4* S = g ? A4 : B4;
        __half* dst = g ? sA : sB;
        float4 w0, w1;
        if (g) { w0 = __ldg(&W4[cf4]); w1 = __ldg(&W4[cf4 + 1]); }

        #pragma unroll
        for (int p = 0; p < 4; p++) {
            int row = rblk * 4 + p;
            float4 f0 = S[row * 64 + cf4];
            float4 f1 = S[row * 64 + cf4 + 1];
            if (g) { f0 = mul4(f0, w0); f1 = mul4(f1, w1); }
            *(uint4*)&dst[row * SST + cf4 * 4] = pack8(f0, f1);
        }
    }
    __syncthreads();

    // ================= phase B: MMA(chunk0) || front-end(chunk1) ============
    wmma::fragment<wmma::accumulator, 16, 16, 16, float> acc[2][2];
    const int wr = (warp >> 1) & 1;
    const int wc = warp & 1;

    if (warp < 4) {
        #pragma unroll
        for (int r = 0; r < 2; r++)
            #pragma unroll
            for (int c = 0; c < 2; c++)
                wmma::fill_fragment(acc[r][c], bias);   // bias folded into init

        const __half* Ab = sA + (wr * 32) * SST;
        const __half* Bb = sB + (wc * 32) * SST;
        #pragma unroll
        for (int kk = 0; kk < 128; kk += 16) {
            wmma::fragment<wmma::matrix_a, 16, 16, 16, __half, wmma::row_major> af[2];
            wmma::fragment<wmma::matrix_b, 16, 16, 16, __half, wmma::col_major> bf[2];
            #pragma unroll
            for (int r = 0; r < 2; r++)
                wmma::load_matrix_sync(af[r], Ab + r * 16 * SST + kk, SST);
            #pragma unroll
            for (int c = 0; c < 2; c++)
                wmma::load_matrix_sync(bf[c], Bb + c * 16 * SST + kk, SST);
            #pragma unroll
            for (int r = 0; r < 2; r++)
                #pragma unroll
                for (int c = 0; c < 2; c++)
                    wmma::mma_sync(acc[r][c], af[r], bf[c], acc[r][c]);
        }
    } else if (warp >= 8) {
        // chunk 1 (f4 cols 32..63) by warps 8-15 (256 threads)
        const int u    = tid - 256;        // 0..255
        const int g    = u >> 7;           // 0 -> B (warps 8-11), 1 -> A (12-15)
        const int uu   = u & 127;
        const int pcol = uu & 15;
        const int rblk = uu >> 4;          // 0..7 -> rows rblk*8+p
        const int cf4  = 32 + pcol * 2;
        const float4* S = g ? A4 : B4;
        __half* dst = g ? sA : sB;
        float4 w0, w1;
        if (g) { w0 = __ldg(&W4[cf4]); w1 = __ldg(&W4[cf4 + 1]); }

        #pragma unroll
        for (int p = 0; p < 8; p++) {
            int row = rblk * 8 + p;
            float4 f0 = S[row * 64 + cf4];
            float4 f1 = S[row * 64 + cf4 + 1];
            if (g) { f0 = mul4(f0, w0); f1 = mul4(f1, w1); }
            *(uint4*)&dst[row * SST + cf4 * 4] = pack8(f0, f1);
        }
    }
    __syncthreads();

    // ================= phase C: MMA(chunk1) + store (warps 0-3) =============
    if (warp >= 4) return;

    {
        const __half* Ab = sA + (wr * 32) * SST;
        const __half* Bb = sB + (wc * 32) * SST;
        #pragma unroll
        for (int kk = 128; kk < 256; kk += 16) {
            wmma::fragment<wmma::matrix_a, 16, 16, 16, __half, wmma::row_major> af[2];
            wmma::fragment<wmma::matrix_b, 16, 16, 16, __half, wmma::col_major> bf[2];
            #pragma unroll
            for (int r = 0; r < 2; r++)
                wmma::load_matrix_sync(af[r], Ab + r * 16 * SST + kk, SST);
            #pragma unroll
            for (int c = 0; c < 2; c++)
                wmma::load_matrix_sync(bf[c], Bb + c * 16 * SST + kk, SST);
            #pragma unroll
            for (int r = 0; r < 2; r++)
                #pragma unroll
                for (int c = 0; c < 2; c++)
                    wmma::mma_sync(acc[r][c], af[r], bf[c], acc[r][c]);
        }
    }

    #pragma unroll
    for (int r = 0; r < 2; r++) {
        #pragma unroll
        for (int c = 0; c < 2; c++) {
            int gi = ti * TILE + wr * 32 + r * 16;
            int gj = tj * TILE + wc * 32 + c * 16;
            float* dst = out + (size_t)bz * L_ * L_ + (size_t)gi * L_ + gj;
            wmma::store_matrix_sync(dst, acc[r][c], L_, wmma::mem_row_major);
        }
    }
}

// ---------------------------------------------------------------------------
// d_in[0] = inputs f32 (2,512,256), d_in[1] = W f32 (512,1), d_in[2] = b f32 (1,)
// d_out   = f32 (2,512,512,1)
// ---------------------------------------------------------------------------
extern "C" void kernel_launch(void* const* d_in, const int* in_sizes, int n_in,
                              void* d_out, int out_size) {
    const float* x    = (const float*)d_in[0];
    const float* W    = (const float*)d_in[1];
    const float* bptr = (const float*)d_in[2];
    float* out = (float*)d_out;

    static bool attr_set = false;
    if (!attr_set) {
        cudaFuncSetAttribute(fused_pairwise_kernel,
                             cudaFuncAttributeMaxDynamicSharedMemorySize, SMEM_BYTES);
        attr_set = true;
    }

    dim3 grid(L_ / TILE, L_ / TILE, B_);   // (8, 8, 2) = 128 CTAs, single wave
    fused_pairwise_kernel<<<grid, THREADS, SMEM_BYTES>>>(x, W, bptr, out);
}

// round 16
// speedup vs baseline: 1.2362x; 1.0258x over previous
#include <cuda_runtime.h>
#include <cuda_fp16.h>
#include <mma.h>
#include <cstdint>

using namespace nvcuda;

// Fixed shapes
#define B_      2
#define L_      512
#define D_      256
#define TILE    64
#define THREADS 512
#define SST     264                      // fp16 row stride: 256 + 8 pad (528B)
#define TEL     (TILE * SST)
#define SMEM_BYTES (2 * TEL * 2)         // 67584 B

// out[b,i,j] = sum_d x[b,i,d]*w1[d]*x[b,j,d] + bias   (symmetric)
// (lin_i - lin_j cancels under (P+P^T)/2; w2 = W[D:,0] dead.)
// fp16 single product, f32 accumulate: rel err ~2.9e-4 < 1e-3 (measured).

__device__ __forceinline__ uint32_t h2(float a, float b) {
    __half2 h = __floats2half2_rn(a, b);
    return *reinterpret_cast<uint32_t*>(&h);
}
__device__ __forceinline__ uint4 pack8(float4 f0, float4 f1) {
    uint4 v;
    v.x = h2(f0.x, f0.y);
    v.y = h2(f0.z, f0.w);
    v.z = h2(f1.x, f1.y);
    v.w = h2(f1.z, f1.w);
    return v;
}
__device__ __forceinline__ float4 mul4(float4 a, float4 w) {
    a.x *= w.x; a.y *= w.y; a.z *= w.z; a.w *= w.w;
    return a;
}

__global__ __launch_bounds__(THREADS, 1)
void fused_pairwise_kernel(const float* __restrict__ x,
                           const float* __restrict__ W,
                           const float* __restrict__ bias_p,
                           float* __restrict__ out) {
    extern __shared__ __align__(16) __half smem[];
    __half* sB = smem;            // fp16(x), j-strip rows
    __half* sA = smem + TEL;      // fp16(x*w1), i-strip rows

    const int bz  = blockIdx.z;
    const int ti  = blockIdx.y;
    const int tj  = blockIdx.x;
    const int tid = threadIdx.x;
    const int warp = tid >> 5;

    const float bias = __ldg(bias_p);

    const float4* A4 = (const float4*)(x + (size_t)(bz * L_ + ti * TILE) * D_);
    const float4* B4 = (const float4*)(x + (size_t)(bz * L_ + tj * TILE) * D_);
    const float4* W4 = (const float4*)W;  // w1 = W[:256] -> f4 cols 0..63

    // ========== phase A: chunk 0 (f4 cols 0..31), all 512 threads ==========
    {
        const int g    = tid >> 8;         // 0 -> B, 1 -> A
        const int u    = tid & 255;
        const int pcol = u & 15;
        const int rblk = u >> 4;           // 0..15 -> rows rblk*4+p
        const int cf4  = pcol * 2;
        const float4* S = g ? A4 : B4;
        __half* dst = g ? sA : sB;
        float4 w0, w1;
        if (g) { w0 = __ldg(&W4[cf4]); w1 = __ldg(&W4[cf4 + 1]); }

        #pragma unroll
        for (int p = 0; p < 4; p++) {
            int row = rblk * 4 + p;
            float4 f0 = S[row * 64 + cf4];
            float4 f1 = S[row * 64 + cf4 + 1];
            if (g) { f0 = mul4(f0, w0); f1 = mul4(f1, w1); }
            *(uint4*)&dst[row * SST + cf4 * 4] = pack8(f0, f1);
        }
    }
    __syncthreads();

    // ========== phase B: MMA(chunk0) by warps 12-15 || fe(chunk1) by 0-11 ==
    wmma::fragment<wmma::accumulator, 16, 16, 16, float> acc[2][2];
    const int mw = warp - 12;             // MMA warp index 0..3 (warps 12-15)
    const int wr = (mw >> 1) & 1;
    const int wc = mw & 1;

    if (warp >= 12) {
        #pragma unroll
        for (int r = 0; r < 2; r++)
            #pragma unroll
            for (int c = 0; c < 2; c++)
                wmma::fill_fragment(acc[r][c], bias);   // bias folded into init

        const __half* Ab = sA + (wr * 32) * SST;
        const __half* Bb = sB + (wc * 32) * SST;
        #pragma unroll
        for (int kk = 0; kk < 128; kk += 16) {
            wmma::fragment<wmma::matrix_a, 16, 16, 16, __half, wmma::row_major> af[2];
            wmma::fragment<wmma::matrix_b, 16, 16, 16, __half, wmma::col_major> bf[2];
            #pragma unroll
            for (int r = 0; r < 2; r++)
                wmma::load_matrix_sync(af[r], Ab + r * 16 * SST + kk, SST);
            #pragma unroll
            for (int c = 0; c < 2; c++)
                wmma::load_matrix_sync(bf[c], Bb + c * 16 * SST + kk, SST);
            #pragma unroll
            for (int r = 0; r < 2; r++)
                #pragma unroll
                for (int c = 0; c < 2; c++)
                    wmma::mma_sync(acc[r][c], af[r], bf[c], acc[r][c]);
        }
    } else {
        // chunk 1 (f4 cols 32..63): 2048 units over 384 threads (warps 0-11)
        // unit: m (matrix), row, pcol -> 2 LDG.128 + pack + 1 STS.128
        for (int u = tid; u < 2048; u += 384) {
            const int m    = u >> 10;          // 0 -> B, 1 -> A
            const int rem  = u & 1023;
            const int row  = rem >> 4;         // 0..63
            const int cf4  = 32 + (rem & 15) * 2;
            const float4* S = m ? A4 : B4;
            __half* dst = m ? sA : sB;
            float4 f0 = S[row * 64 + cf4];
            float4 f1 = S[row * 64 + cf4 + 1];
            if (m) {
                f0 = mul4(f0, __ldg(&W4[cf4]));
                f1 = mul4(f1, __ldg(&W4[cf4 + 1]));
            }
            *(uint4*)&dst[row * SST + cf4 * 4] = pack8(f0, f1);
        }
    }
    __syncthreads();

    // ========== phase C: MMA(chunk1) + store (warps 12-15) ==========
    if (warp < 12) return;

    {
        const __half* Ab = sA + (wr * 32) * SST;
        const __half* Bb = sB + (wc * 32) * SST;
        #pragma unroll
        for (int kk = 128; kk < 256; kk += 16) {
            wmma::fragment<wmma::matrix_a, 16, 16, 16, __half, wmma::row_major> af[2];
            wmma::fragment<wmma::matrix_b, 16, 16, 16, __half, wmma::col_major> bf[2];
            #pragma unroll
            for (int r = 0; r < 2; r++)
                wmma::load_matrix_sync(af[r], Ab + r * 16 * SST + kk, SST);
            #pragma unroll
            for (int c = 0; c < 2; c++)
                wmma::load_matrix_sync(bf[c], Bb + c * 16 * SST + kk, SST);
            #pragma unroll
            for (int r = 0; r < 2; r++)
                #pragma unroll
                for (int c = 0; c < 2; c++)
                    wmma::mma_sync(acc[r][c], af[r], bf[c], acc[r][c]);
        }
    }

    #pragma unroll
    for (int r = 0; r < 2; r++) {
        #pragma unroll
        for (int c = 0; c < 2; c++) {
            int gi = ti * TILE + wr * 32 + r * 16;
            int gj = tj * TILE + wc * 32 + c * 16;
            float* dst = out + (size_t)bz * L_ * L_ + (size_t)gi * L_ + gj;
            wmma::store_matrix_sync(dst, acc[r][c], L_, wmma::mem_row_major);
        }
    }
}

// ---------------------------------------------------------------------------
// d_in[0] = inputs f32 (2,512,256), d_in[1] = W f32 (512,1), d_in[2] = b f32 (1,)
// d_out   = f32 (2,512,512,1)
// ---------------------------------------------------------------------------
extern "C" void kernel_launch(void* const* d_in, const int* in_sizes, int n_in,
                              void* d_out, int out_size) {
    const float* x    = (const float*)d_in[0];
    const float* W    = (const float*)d_in[1];
    const float* bptr = (const float*)d_in[2];
    float* out = (float*)d_out;

    static bool attr_set = false;
    if (!attr_set) {
        cudaFuncSetAttribute(fused_pairwise_kernel,
                             cudaFuncAttributeMaxDynamicSharedMemorySize, SMEM_BYTES);
        attr_set = true;
    }

    dim3 grid(L_ / TILE, L_ / TILE, B_);   // (8, 8, 2) = 128 CTAs, single wave
    fused_pairwise_kernel<<<grid, THREADS, SMEM_BYTES>>>(x, W, bptr, out);
}